// round 2
// baseline (speedup 1.0000x reference)
#include <cuda_runtime.h>

// Grid constants (match reference)
#define N_PIX_HI 512
#define NV_HI    256
#define N_PIX_LO 128
#define NV_LO    64
#define PIX_HI_F      0.025f
#define FOV_HALF_HI_F 6.3875f
#define DV_HI_F       3.125f
#define VEL0_HI_F     -404.6875f
#define M_POINTS 2000000
#define OUT_ELEMS (NV_LO * N_PIX_LO * N_PIX_LO)   // 1,048,576

__global__ void zero_out_kernel(float4* __restrict__ out, int n4) {
    int i = blockIdx.x * blockDim.x + threadIdx.x;
    if (i < n4) out[i] = make_float4(0.f, 0.f, 0.f, 0.f);
}

__global__ void splat_kernel(const float* __restrict__ ra,
                             const float* __restrict__ dec,
                             const float* __restrict__ vel,
                             const float* __restrict__ flux,
                             float* __restrict__ out,
                             int n) {
    int i = blockIdx.x * blockDim.x + threadIdx.x;
    if (i >= n) return;

    float x = (ra[i]  + FOV_HALF_HI_F) / PIX_HI_F;
    float y = (dec[i] + FOV_HALF_HI_F) / PIX_HI_F;
    float v = (vel[i] - VEL0_HI_F)     / DV_HI_F;

    float xf = floorf(x), yf = floorf(y), vf = floorf(v);
    int ix0 = (int)xf, iy0 = (int)yf, iv0 = (int)vf;
    float fx = x - xf, fy = y - yf, fv = v - vf;

    bool valid = (ix0 >= 0) & (ix0 < N_PIX_HI - 1) &
                 (iy0 >= 0) & (iy0 < N_PIX_HI - 1) &
                 (iv0 >= 0) & (iv0 < NV_HI - 1);
    if (!valid) return;   // reference splats zero flux for invalid points

    float f = flux[i] * (1.0f / 64.0f);   // block-mean folded in

    // Per axis: map the two hi-res corners to low-res cells; merge if equal.
    int cx[2]; float wx[2]; int nx;
    cx[0] = ix0 >> 2;
    if ((ix0 >> 2) == ((ix0 + 1) >> 2)) { wx[0] = 1.0f; nx = 1; }
    else { wx[0] = 1.0f - fx; cx[1] = (ix0 + 1) >> 2; wx[1] = fx; nx = 2; }

    int cy[2]; float wy[2]; int ny;
    cy[0] = iy0 >> 2;
    if ((iy0 >> 2) == ((iy0 + 1) >> 2)) { wy[0] = 1.0f; ny = 1; }
    else { wy[0] = 1.0f - fy; cy[1] = (iy0 + 1) >> 2; wy[1] = fy; ny = 2; }

    int cv[2]; float wv[2]; int nv;
    cv[0] = iv0 >> 2;
    if ((iv0 >> 2) == ((iv0 + 1) >> 2)) { wv[0] = 1.0f; nv = 1; }
    else { wv[0] = 1.0f - fv; cv[1] = (iv0 + 1) >> 2; wv[1] = fv; nv = 2; }

    for (int k = 0; k < nv; k++) {
        float fwv = f * wv[k];
        int basev = cv[k] * N_PIX_LO;
        for (int j = 0; j < ny; j++) {
            float fwvy = fwv * wy[j];
            int basevy = (basev + cy[j]) * N_PIX_LO;
            for (int ii = 0; ii < nx; ii++) {
                atomicAdd(&out[basevy + cx[ii]], fwvy * wx[ii]);
            }
        }
    }
}

extern "C" void kernel_launch(void* const* d_in, const int* in_sizes, int n_in,
                              void* d_out, int out_size) {
    const float* ra   = (const float*)d_in[0];
    const float* dec  = (const float*)d_in[1];
    const float* vel  = (const float*)d_in[2];
    const float* flux = (const float*)d_in[3];
    float* out = (float*)d_out;
    int n = in_sizes[0];

    int n4 = OUT_ELEMS / 4;
    zero_out_kernel<<<(n4 + 255) / 256, 256>>>((float4*)out, n4);

    splat_kernel<<<(n + 255) / 256, 256>>>(ra, dec, vel, flux, out, n);
}